// round 6
// baseline (speedup 1.0000x reference)
#include <cuda_runtime.h>

// QLSTM: B=512, T=1024, IN=1, H=64.
// 128 blocks x 512 threads, 4 batches/block, persistent over all T.
// Thread (u, gs, ks, bp):
//   u  = hidden unit (0..63)         = (t&7) + 8*((t>>5)&7)
//   gs = gate split (bit 3 of lane)  : 0 -> {i,f}, 1 -> {g,o}
//   ks = k split    (bit 4 of lane)  : half of the 64-wide contraction
//   bp = batch pair (t>>8)           : batches {2bp, 2bp+1}
// W_hh slice per thread: 2 gates x 32 k packed as 32 u64 (64 regs) ->
// register-resident without spilling. FFMA2 (fma.rn.f32x2) does 2 MACs/instr.
// h stored duplicated {h,h} in shared, double-buffered, padded so the two
// ks-half chunks are bank-disjoint. k-partials combine via shfl_xor(16);
// gate halves exchange via shfl_xor(8). One barrier per step.

#define TPB 512
#define NB  4
#define TSTEPS 1024
#define HSTRIDE 34   // u64 per ks-half: 32 data + 2 pad (272 B -> +4 banks)

typedef unsigned long long u64t;

struct Smem {
  u64t hd[2][NB][2][HSTRIDE];       // {h,h} double-buffered: 4352 B
  union {
    float wstage[256 * 64];         // W_hh staging: 64 KB
    u64t  xsd[NB][TSTEPS];          // {x,x} packed input: 32 KB
  } un;
};

__device__ __forceinline__ u64t pack2(float lo, float hi) {
  u64t r;
  asm("mov.b64 %0, {%1, %2};" : "=l"(r) : "f"(lo), "f"(hi));
  return r;
}
__device__ __forceinline__ void unpack2(float& lo, float& hi, u64t v) {
  asm("mov.b64 {%0, %1}, %2;" : "=f"(lo), "=f"(hi) : "l"(v));
}
__device__ __forceinline__ u64t ffma2(u64t a, u64t b, u64t c) {
  u64t d;
  asm("fma.rn.f32x2 %0, %1, %2, %3;" : "=l"(d) : "l"(a), "l"(b), "l"(c));
  return d;
}
__device__ __forceinline__ u64t addx2(u64t a, u64t b) {
  u64t d;
  asm("add.rn.f32x2 %0, %1, %2;" : "=l"(d) : "l"(a), "l"(b));
  return d;
}

__device__ __forceinline__ float sigf(float v) {
  return __fdividef(1.0f, 1.0f + __expf(-v));
}
__device__ __forceinline__ float tanhf_fast(float v) {
  return 1.0f - __fdividef(2.0f, __expf(2.0f * v) + 1.0f);
}

extern __shared__ char smem_raw[];

__global__ void __launch_bounds__(TPB, 1) qlstm_kernel(
    const float* __restrict__ x,      // [B, T, 1]
    const float* __restrict__ W_ih,   // [256, 1]
    const float* __restrict__ W_hh,   // [256, 64]
    const float* __restrict__ b_ih,   // [256]
    const float* __restrict__ b_hh,   // [256]
    const float* __restrict__ W_lin,  // [1, 64]
    const float* __restrict__ b_lin,  // [1]
    float* __restrict__ out)          // [B]
{
  Smem& s = *reinterpret_cast<Smem*>(smem_raw);
  const int t  = threadIdx.x;
  const int ul = t & 7;
  const int gs = (t >> 3) & 1;        // lane bit 3
  const int ks = (t >> 4) & 1;        // lane bit 4
  const int uh = (t >> 5) & 7;
  const int bp = (t >> 8) & 1;
  const int u  = ul + 8 * uh;         // 0..63
  const int b0 = 2 * bp;
  const int b1 = b0 + 1;
  const int batch0 = blockIdx.x * NB;

  // ---- stage W_hh into shared (coalesced) ----
  {
    const float4* src = reinterpret_cast<const float4*>(W_hh);
    float4* dst = reinterpret_cast<float4*>(s.un.wstage);
    for (int i = t; i < 256 * 64 / 4; i += TPB) dst[i] = src[i];
  }
  __syncthreads();

  // ---- scatter my W slice to registers: 2 gates x 32 k packed ----
  const int r0 = gs * 128 + u;        // gate row i or g
  const int r1 = r0 + 64;             // gate row f or o
  const int k0 = 32 * ks;             // my k range [k0, k0+32)
  u64t Wreg[32];
#pragma unroll
  for (int kk = 0; kk < 32; kk++)
    Wreg[kk] = pack2(s.un.wstage[r0 * 64 + k0 + kk],
                     s.un.wstage[r1 * 64 + k0 + kk]);
  __syncthreads();                    // wstage dead; union reused for x

  // ---- stage x duplicated {x,x}; zero h buffer 0 ----
  for (int i = t; i < NB * TSTEPS; i += TPB) {
    int bb = i >> 10, tt = i & (TSTEPS - 1);
    float xv = x[(batch0 + bb) * TSTEPS + tt];
    s.un.xsd[bb][tt] = pack2(xv, xv);
  }
  for (int i = t; i < 2 * NB * 2 * HSTRIDE; i += TPB)
    (&s.hd[0][0][0][0])[i] = 0ull;

  const u64t bias2 = pack2(b_ih[r0] + b_hh[r0], b_ih[r1] + b_hh[r1]);
  const u64t wih2  = pack2(W_ih[r0], W_ih[r1]);
  __syncthreads();

  float cA = 0.0f, cB = 0.0f;
  int pb = 0;

  for (int step = 0; step < TSTEPS; step++) {
    // bias + W_ih*x only on ks==0 (avoid double count after combine)
    u64t a0, a1;
    if (ks == 0) {
      a0 = ffma2(wih2, s.un.xsd[b0][step], bias2);
      a1 = ffma2(wih2, s.un.xsd[b1][step], bias2);
    } else {
      a0 = 0ull;
      a1 = 0ull;
    }

    const ulonglong2* __restrict__ h0p =
        reinterpret_cast<const ulonglong2*>(&s.hd[pb][b0][ks][0]);
    const ulonglong2* __restrict__ h1p =
        reinterpret_cast<const ulonglong2*>(&s.hd[pb][b1][ks][0]);
#pragma unroll
    for (int j = 0; j < 16; j++) {
      ulonglong2 H0 = h0p[j];         // two duplicated h values (16B)
      ulonglong2 H1 = h1p[j];
      a0 = ffma2(Wreg[2 * j],     H0.x, a0);
      a1 = ffma2(Wreg[2 * j],     H1.x, a1);
      a0 = ffma2(Wreg[2 * j + 1], H0.y, a0);
      a1 = ffma2(Wreg[2 * j + 1], H1.y, a1);
    }

    // combine k-partials with ks-partner (lane ^ 16); both get full sums
    a0 = addx2(a0, __shfl_xor_sync(0xFFFFFFFFu, a0, 16));
    a1 = addx2(a1, __shfl_xor_sync(0xFFFFFFFFu, a1, 16));

    // activations on my two gates, both batches
    float p0, q0, p1, q1;
    unpack2(p0, q0, a0);
    unpack2(p1, q1, a1);
    float A0, B0, A1, B1;
    if (gs == 0) {                    // i, f
      A0 = sigf(p0); B0 = sigf(q0);
      A1 = sigf(p1); B1 = sigf(q1);
    } else {                          // g, o
      A0 = tanhf_fast(p0); B0 = sigf(q0);
      A1 = tanhf_fast(p1); B1 = sigf(q1);
    }
    // exchange with gs-partner (lane ^ 8)
    float oA0 = __shfl_xor_sync(0xFFFFFFFFu, A0, 8);
    float oB0 = __shfl_xor_sync(0xFFFFFFFFu, B0, 8);
    float oA1 = __shfl_xor_sync(0xFFFFFFFFu, A1, 8);
    float oB1 = __shfl_xor_sync(0xFFFFFFFFu, B1, 8);
    float i0 = gs ? oA0 : A0, f0 = gs ? oB0 : B0;
    float g0 = gs ? A0 : oA0, o0 = gs ? B0 : oB0;
    float i1 = gs ? oA1 : A1, f1 = gs ? oB1 : B1;
    float g1 = gs ? A1 : oA1, o1 = gs ? B1 : oB1;

    cA = fmaf(f0, cA, i0 * g0);
    cB = fmaf(f1, cB, i1 * g1);
    float hn0 = o0 * tanhf_fast(cA);
    float hn1 = o1 * tanhf_fast(cB);

    // one writer per (unit, batch): ks==0 lanes; gs picks batch of the pair
    if (ks == 0) {
      float hn = gs ? hn1 : hn0;
      s.hd[pb ^ 1][b0 + gs][u >> 5][u & 31] = pack2(hn, hn);
    }
    pb ^= 1;
    __syncthreads();                  // double buffer -> single barrier
  }

  // final linear: out[b] = h_final[b] . W_lin + b_lin
  if (t < NB) {
    float sum = b_lin[0];
#pragma unroll
    for (int k = 0; k < 64; k++) {
      float lo, hi;
      unpack2(lo, hi, s.hd[pb][t][k >> 5][k & 31]);
      sum = fmaf(lo, W_lin[k], sum);
    }
    out[batch0 + t] = sum;
  }
}

extern "C" void kernel_launch(void* const* d_in, const int* in_sizes, int n_in,
                              void* d_out, int out_size) {
  const float* x     = (const float*)d_in[0];
  const float* W_ih  = (const float*)d_in[1];
  const float* W_hh  = (const float*)d_in[2];
  const float* b_ih  = (const float*)d_in[3];
  const float* b_hh  = (const float*)d_in[4];
  const float* W_lin = (const float*)d_in[5];
  const float* b_lin = (const float*)d_in[6];
  float* out = (float*)d_out;

  const int B = out_size;  // 512
  const int nblocks = B / NB;

  cudaFuncSetAttribute(qlstm_kernel,
                       cudaFuncAttributeMaxDynamicSharedMemorySize,
                       (int)sizeof(Smem));
  qlstm_kernel<<<nblocks, TPB, sizeof(Smem)>>>(x, W_ih, W_hh, b_ih, b_hh,
                                               W_lin, b_lin, out);
}

// round 8
// speedup vs baseline: 1.9658x; 1.9658x over previous
#include <cuda_runtime.h>

// QLSTM: B=512, T=1024, IN=1, H=64.
// 128 blocks x 256 threads, 4 batches/block, persistent over all T.
// Thread (u, gs, ks): lane bits [0:2]=u-low, [3]=gs, [4]=ks; u-high = warp id.
//   gs: gate split 0->{i,f}, 1->{g,o}. ks: k-half split of the 64 contraction.
// Each thread handles ALL 4 batches. W slice = 2 gates x 32 k packed as
// 32 u64 (64 regs, register-resident; 256-reg cap at TPB=256 -> no spill).
// fma.rn.f32x2 = 2 MACs/instr. h stored duplicated {h,h} in shared as
// [2 buf][4 batch][2 half][34] u64 (halves pad-offset -> bank-disjoint).
// k-partials combine via shfl_xor(16). Gate exchange via shfl_xor(8):
// each lane SENDS a[bstar^2] (partner's batch) and KEEPS a[bstar], then
// owns (u, bstar) end-to-end: computes c,h, writes one dup u64.

#define TPB 256
#define NB  4
#define TSTEPS 1024
#define HHALF 34   // u64 per k-half: 32 data + 2 pad (272 B -> +4 banks)

typedef unsigned long long u64t;

struct Smem {
  u64t hd[2][NB][2][HHALF];         // {h,h} dup, double-buffered: 4352 B
  union {
    float wstage[256 * 64];         // W_hh staging: 64 KB
    u64t  xsd[NB][TSTEPS];          // {x,x} dup input: 32 KB
  } un;
};

__device__ __forceinline__ u64t pack2(float lo, float hi) {
  u64t r;
  asm("mov.b64 %0, {%1, %2};" : "=l"(r) : "f"(lo), "f"(hi));
  return r;
}
__device__ __forceinline__ void unpack2(float& lo, float& hi, u64t v) {
  asm("mov.b64 {%0, %1}, %2;" : "=f"(lo), "=f"(hi) : "l"(v));
}
__device__ __forceinline__ u64t ffma2(u64t a, u64t b, u64t c) {
  u64t d;
  asm("fma.rn.f32x2 %0, %1, %2, %3;" : "=l"(d) : "l"(a), "l"(b), "l"(c));
  return d;
}
__device__ __forceinline__ u64t addx2(u64t a, u64t b) {
  u64t d;
  asm("add.rn.f32x2 %0, %1, %2;" : "=l"(d) : "l"(a), "l"(b));
  return d;
}

__device__ __forceinline__ float sigf(float v) {
  return __fdividef(1.0f, 1.0f + __expf(-v));
}
__device__ __forceinline__ float tanhf_fast(float v) {
  return 1.0f - __fdividef(2.0f, __expf(2.0f * v) + 1.0f);
}

extern __shared__ char smem_raw[];

__global__ void __launch_bounds__(TPB, 1) qlstm_kernel(
    const float* __restrict__ x,      // [B, T, 1]
    const float* __restrict__ W_ih,   // [256, 1]
    const float* __restrict__ W_hh,   // [256, 64]
    const float* __restrict__ b_ih,   // [256]
    const float* __restrict__ b_hh,   // [256]
    const float* __restrict__ W_lin,  // [1, 64]
    const float* __restrict__ b_lin,  // [1]
    float* __restrict__ out)          // [B]
{
  Smem& s = *reinterpret_cast<Smem*>(smem_raw);
  const int t  = threadIdx.x;
  const int ul = t & 7;
  const int gs = (t >> 3) & 1;        // lane bit 3
  const int ks = (t >> 4) & 1;        // lane bit 4
  const int uh = t >> 5;              // warp id 0..7
  const int u  = ul + 8 * uh;         // 0..63
  const int bstar = 2 * gs + ks;      // this lane's epilogue batch
  const int batch0 = blockIdx.x * NB;

  // ---- stage W_hh into shared (coalesced) ----
  {
    const float4* src = reinterpret_cast<const float4*>(W_hh);
    float4* dst = reinterpret_cast<float4*>(s.un.wstage);
    for (int i = t; i < 256 * 64 / 4; i += TPB) dst[i] = src[i];
  }
  __syncthreads();

  // ---- my W slice: 2 gates x 32 k packed (64 regs) ----
  const int r0 = gs * 128 + u;        // gate row i or g
  const int r1 = r0 + 64;             // gate row f or o
  const int k0 = 32 * ks;             // my k range [k0, k0+32)
  u64t Wreg[32];
#pragma unroll
  for (int kk = 0; kk < 32; kk++)
    Wreg[kk] = pack2(s.un.wstage[r0 * 64 + k0 + kk],
                     s.un.wstage[r1 * 64 + k0 + kk]);
  __syncthreads();                    // wstage dead; union reused for x

  // ---- stage x duplicated {x,x}; zero both h buffers ----
  for (int i = t; i < NB * TSTEPS; i += TPB) {
    int bb = i >> 10, tt = i & (TSTEPS - 1);
    float xv = x[(batch0 + bb) * TSTEPS + tt];
    s.un.xsd[bb][tt] = pack2(xv, xv);
  }
  for (int i = t; i < 2 * NB * 2 * HHALF; i += TPB)
    (&s.hd[0][0][0][0])[i] = 0ull;

  const u64t bias2 = pack2(b_ih[r0] + b_hh[r0], b_ih[r1] + b_hh[r1]);
  const u64t wih2  = pack2(W_ih[r0], W_ih[r1]);
  __syncthreads();

  float c = 0.0f;                     // cell state for (u, bstar)
  int pb = 0;

  for (int step = 0; step < TSTEPS; step++) {
    // bias + W_ih*x only on ks==0 (avoid double count after combine)
    u64t a0, a1, a2, a3;
    if (ks == 0) {
      a0 = ffma2(wih2, s.un.xsd[0][step], bias2);
      a1 = ffma2(wih2, s.un.xsd[1][step], bias2);
      a2 = ffma2(wih2, s.un.xsd[2][step], bias2);
      a3 = ffma2(wih2, s.un.xsd[3][step], bias2);
    } else {
      a0 = a1 = a2 = a3 = 0ull;
    }

    // my k-half of h for each batch: u64 elements [0,32) of half `ks`
    const ulonglong2* __restrict__ h0p =
        reinterpret_cast<const ulonglong2*>(&s.hd[pb][0][ks][0]);
    const ulonglong2* __restrict__ h1p =
        reinterpret_cast<const ulonglong2*>(&s.hd[pb][1][ks][0]);
    const ulonglong2* __restrict__ h2p =
        reinterpret_cast<const ulonglong2*>(&s.hd[pb][2][ks][0]);
    const ulonglong2* __restrict__ h3p =
        reinterpret_cast<const ulonglong2*>(&s.hd[pb][3][ks][0]);
#pragma unroll
    for (int j = 0; j < 16; j++) {
      ulonglong2 H0 = h0p[j];         // 2 dup h values; 2 addrs/warp,
      ulonglong2 H1 = h1p[j];         // bank-disjoint (272 B apart)
      ulonglong2 H2 = h2p[j];
      ulonglong2 H3 = h3p[j];
      u64t w0 = Wreg[2 * j], w1 = Wreg[2 * j + 1];
      a0 = ffma2(w0, H0.x, a0);
      a1 = ffma2(w0, H1.x, a1);
      a2 = ffma2(w0, H2.x, a2);
      a3 = ffma2(w0, H3.x, a3);
      a0 = ffma2(w1, H0.y, a0);
      a1 = ffma2(w1, H1.y, a1);
      a2 = ffma2(w1, H2.y, a2);
      a3 = ffma2(w1, H3.y, a3);
    }

    // combine k halves with ks-partner (lane ^ 16); both get full sums
    a0 = addx2(a0, __shfl_xor_sync(0xFFFFFFFFu, a0, 16));
    a1 = addx2(a1, __shfl_xor_sync(0xFFFFFFFFu, a1, 16));
    a2 = addx2(a2, __shfl_xor_sync(0xFFFFFFFFu, a2, 16));
    a3 = addx2(a3, __shfl_xor_sync(0xFFFFFFFFu, a3, 16));

    // gate exchange with gs-partner (lane ^ 8).
    // I keep a[bstar] (my batch, my gate pair). My partner's bstar is
    // bstar^2, so I SEND a[bstar^2] and RECEIVE my batch's other pair.
    u64t mine, tosend;
    {
      // select by bstar: 0..3
      u64t s0 = (bstar & 1) ? a1 : a0;
      u64t s1 = (bstar & 1) ? a3 : a2;
      mine   = (bstar & 2) ? s1 : s0;
      tosend = (bstar & 2) ? s0 : s1;   // a[bstar ^ 2]
    }
    u64t partner = __shfl_xor_sync(0xFFFFFFFFu, tosend, 8);

    float p0, p1, q0, q1;
    unpack2(p0, p1, mine);            // gs=0: {i,f}; gs=1: {g,o}
    unpack2(q0, q1, partner);         // other pair, SAME batch
    float iv, fv, gv, ov;
    if (gs == 0) { iv = p0; fv = p1; gv = q0; ov = q1; }
    else         { iv = q0; fv = q1; gv = p0; ov = p1; }

    iv = sigf(iv);
    fv = sigf(fv);
    gv = tanhf_fast(gv);
    ov = sigf(ov);
    c = fmaf(fv, c, iv * gv);
    float hn = ov * tanhf_fast(c);

    // one writer per (u, batch)
    s.hd[pb ^ 1][bstar][u >> 5][u & 31] = pack2(hn, hn);
    pb ^= 1;
    __syncthreads();                  // double buffer -> one barrier
  }

  // final linear: out[b] = h_final[b] . W_lin + b_lin
  if (t < NB) {
    float sum = b_lin[0];
#pragma unroll
    for (int k = 0; k < 64; k++) {
      float lo, hi;
      unpack2(lo, hi, s.hd[pb][t][k >> 5][k & 31]);
      sum = fmaf(lo, W_lin[k], sum);
    }
    out[batch0 + t] = sum;
  }
}

extern "C" void kernel_launch(void* const* d_in, const int* in_sizes, int n_in,
                              void* d_out, int out_size) {
  const float* x     = (const float*)d_in[0];
  const float* W_ih  = (const float*)d_in[1];
  const float* W_hh  = (const float*)d_in[2];
  const float* b_ih  = (const float*)d_in[3];
  const float* b_hh  = (const float*)d_in[4];
  const float* W_lin = (const float*)d_in[5];
  const float* b_lin = (const float*)d_in[6];
  float* out = (float*)d_out;

  const int B = out_size;  // 512
  const int nblocks = B / NB;

  cudaFuncSetAttribute(qlstm_kernel,
                       cudaFuncAttributeMaxDynamicSharedMemorySize,
                       (int)sizeof(Smem));
  qlstm_kernel<<<nblocks, TPB, sizeof(Smem)>>>(x, W_ih, W_hh, b_ih, b_hh,
                                               W_lin, b_lin, out);
}